// round 1
// baseline (speedup 1.0000x reference)
#include <cuda_runtime.h>
#include <math.h>
#include <stdint.h>

#define NU_ 100000
#define ND_ 150000
#define NI_ 120000
#define NP_ 80000
#define E_  500000
#define HIDN 128

// ---------------- scratch (static device globals; no allocation) ----------------
__device__ float g_hu[2][(size_t)NU_ * HIDN];
__device__ float g_hd[2][(size_t)ND_ * HIDN];
__device__ float g_hi[2][(size_t)NI_ * HIDN];
__device__ float g_hp[2][(size_t)NP_ * HIDN];
__device__ float g_fs[(size_t)ND_ * HIDN];   // max src-count = ND
__device__ float g_el[ND_ * 4];
__device__ float g_er[ND_ * 4];
__device__ float g_eb[E_ * 4];
__device__ float g_m[ND_ * 4];
__device__ float g_s[ND_ * 4];
__device__ float g_wal[128 * 4];
__device__ float g_war[128 * 4];

// ---------------- device helpers ----------------
__device__ __forceinline__ void redAdd4(float* p, float4 v) {
    asm volatile("red.global.add.v4.f32 [%0], {%1,%2,%3,%4};"
                 :: "l"(p), "f"(v.x), "f"(v.y), "f"(v.z), "f"(v.w) : "memory");
}

__device__ __forceinline__ void atomicMaxF(float* addr, float val) {
    if (val >= 0.0f) atomicMax((int*)addr, __float_as_int(val));
    else             atomicMin((unsigned int*)addr, __float_as_uint(val));
}

__device__ __forceinline__ float lrelu(float x) { return x > 0.0f ? x : 0.2f * x; }

// ---------------- GEMM: C[N,128] = A[N,K] @ B[K,128] (+bias)(+relu) ----------------
// 64x128 block tile, BK=32, 256 threads, 4x8 microtile per thread.
__global__ __launch_bounds__(256) void gemm128(
    const float* __restrict__ A, const float* __restrict__ B,
    const float* __restrict__ bias, float* __restrict__ C,
    int N, int K, int act)
{
    __shared__ float As[32][68];   // [k][row]
    __shared__ float Bs[32][128];  // [k][col]
    const int tid = threadIdx.x;
    const int tx = tid & 15, ty = tid >> 4;
    const int row0 = blockIdx.x * 64;

    float acc[4][8];
#pragma unroll
    for (int i = 0; i < 4; i++)
#pragma unroll
        for (int j = 0; j < 8; j++) acc[i][j] = 0.0f;

    for (int kk = 0; kk < K; kk += 32) {
        // load A tile (64 rows x 32 k): 512 float4, 2 per thread
#pragma unroll
        for (int l = 0; l < 2; l++) {
            int f = tid + l * 256;
            int r = f >> 3;
            int c4 = (f & 7) * 4;
            int gr = row0 + r;
            float4 v = make_float4(0.f, 0.f, 0.f, 0.f);
            if (gr < N) v = *(const float4*)(A + (size_t)gr * K + kk + c4);
            As[c4 + 0][r] = v.x; As[c4 + 1][r] = v.y;
            As[c4 + 2][r] = v.z; As[c4 + 3][r] = v.w;
        }
        // load B tile (32 k x 128 cols): 1024 float4, 4 per thread
#pragma unroll
        for (int l = 0; l < 4; l++) {
            int f = tid + l * 256;
            int r = f >> 5;
            int c4 = (f & 31) * 4;
            *(float4*)&Bs[r][c4] = *(const float4*)(B + (size_t)(kk + r) * HIDN + c4);
        }
        __syncthreads();
#pragma unroll
        for (int k = 0; k < 32; k++) {
            float a[4], b[8];
#pragma unroll
            for (int i = 0; i < 4; i++) a[i] = As[k][ty * 4 + i];
#pragma unroll
            for (int j = 0; j < 8; j++) b[j] = Bs[k][tx * 8 + j];
#pragma unroll
            for (int i = 0; i < 4; i++)
#pragma unroll
                for (int j = 0; j < 8; j++) acc[i][j] += a[i] * b[j];
        }
        __syncthreads();
    }
#pragma unroll
    for (int i = 0; i < 4; i++) {
        int r = row0 + ty * 4 + i;
        if (r < N) {
#pragma unroll
            for (int j = 0; j < 8; j++) {
                int c = tx * 8 + j;
                float v = acc[i][j];
                if (bias) v += bias[c];
                if (act == 1 && v < 0.0f) v = 0.0f;
                C[(size_t)r * HIDN + c] = v;
            }
        }
    }
}

// ---------------- narrow GEMM: out[N,NOUT] = H[N,128] @ w[128,NOUT] (+bias), NOUT<=4 ----------------
__global__ void rowdot(const float* __restrict__ Hm, const float* __restrict__ w,
                       const float* __restrict__ bias, float* __restrict__ out,
                       int N, int NOUT)
{
    __shared__ float ws[128 * 4];
    for (int i = threadIdx.x; i < 128 * NOUT; i += blockDim.x) ws[i] = w[i];
    __syncthreads();
    int gwarp = (blockIdx.x * blockDim.x + threadIdx.x) >> 5;
    int lane = threadIdx.x & 31;
    int nwarps = (gridDim.x * blockDim.x) >> 5;
    for (int row = gwarp; row < N; row += nwarps) {
        float4 h = *(const float4*)(Hm + (size_t)row * HIDN + lane * 4);
        float acc[4] = {0.f, 0.f, 0.f, 0.f};
        const float hv[4] = {h.x, h.y, h.z, h.w};
#pragma unroll
        for (int q = 0; q < 4; q++) {
            int k = lane * 4 + q;
            for (int o = 0; o < NOUT; o++) acc[o] += hv[q] * ws[k * NOUT + o];
        }
#pragma unroll
        for (int off = 16; off; off >>= 1)
            for (int o = 0; o < 4; o++) acc[o] += __shfl_down_sync(0xffffffffu, acc[o], off);
        if (lane == 0)
            for (int o = 0; o < NOUT; o++)
                out[(size_t)row * NOUT + o] = acc[o] + (bias ? bias[o] : 0.0f);
    }
}

// ---------------- fold attention vectors into W: wal[k,h] = sum_d W[k,h*32+d]*al[h,d] ----------------
__global__ void prep_attn_w(const float* __restrict__ W, const float* __restrict__ al,
                            const float* __restrict__ ar,
                            float* __restrict__ wal, float* __restrict__ war)
{
    int k = threadIdx.x;  // 128
#pragma unroll
    for (int h = 0; h < 4; h++) {
        float sl = 0.f, sr = 0.f;
#pragma unroll
        for (int d = 0; d < 32; d++) {
            float wv = W[k * 128 + h * 32 + d];
            sl += wv * al[h * 32 + d];
            sr += wv * ar[h * 32 + d];
        }
        wal[k * 4 + h] = sl;
        war[k * 4 + h] = sr;
    }
}

__global__ void init_neg_inf(float* __restrict__ p, int n) {
    int i = blockIdx.x * blockDim.x + threadIdx.x;
    if (i < n) p[i] = -INFINITY;
}

__global__ void fix_m(float* __restrict__ p, int n) {
    int i = blockIdx.x * blockDim.x + threadIdx.x;
    if (i < n) { float v = p[i]; if (!isfinite(v)) p[i] = 0.0f; }
}

// ---------------- edge pass A: e = lrelu(el[src]+er[dst]); segment max ----------------
__global__ void edge_max_k(const int* __restrict__ src, const int* __restrict__ dst,
                           const float* __restrict__ el, const float* __restrict__ er,
                           float* __restrict__ eb, float* __restrict__ m, int E)
{
    int e = blockIdx.x * blockDim.x + threadIdx.x;
    if (e >= E) return;
    int sn = src[e], dn = dst[e];
    float4 l = *(const float4*)(el + (size_t)sn * 4);
    float4 r = *(const float4*)(er + (size_t)dn * 4);
    float4 v;
    v.x = lrelu(l.x + r.x); v.y = lrelu(l.y + r.y);
    v.z = lrelu(l.z + r.z); v.w = lrelu(l.w + r.w);
    *(float4*)(eb + (size_t)e * 4) = v;
    atomicMaxF(&m[dn * 4 + 0], v.x);
    atomicMaxF(&m[dn * 4 + 1], v.y);
    atomicMaxF(&m[dn * 4 + 2], v.z);
    atomicMaxF(&m[dn * 4 + 3], v.w);
}

// ---------------- edge pass B: ex = exp(e - m[dst]); segment sum ----------------
__global__ void edge_exp_k(const int* __restrict__ dst, float* __restrict__ eb,
                           const float* __restrict__ m, float* __restrict__ s, int E)
{
    int e = blockIdx.x * blockDim.x + threadIdx.x;
    if (e >= E) return;
    int dn = dst[e];
    float4 v = *(const float4*)(eb + (size_t)e * 4);
    float4 mm = *(const float4*)(m + (size_t)dn * 4);
    v.x = expf(v.x - mm.x); v.y = expf(v.y - mm.y);
    v.z = expf(v.z - mm.z); v.w = expf(v.w - mm.w);
    *(float4*)(eb + (size_t)e * 4) = v;
    redAdd4(s + (size_t)dn * 4, v);
}

// ---------------- edge pass C: out[dst] += fs[src] * (ex/s[dst]); warp per edge ----------------
__global__ void edge_msg_k(const int* __restrict__ src, const int* __restrict__ dst,
                           const float* __restrict__ eb, const float* __restrict__ s,
                           const float* __restrict__ fs, float* __restrict__ out, int E)
{
    int gid = blockIdx.x * blockDim.x + threadIdx.x;
    int warp = gid >> 5, lane = gid & 31;
    int nwarps = (gridDim.x * blockDim.x) >> 5;
    for (int e = warp; e < E; e += nwarps) {
        int sn = src[e], dn = dst[e];
        int h = lane >> 3;
        float a = eb[(size_t)e * 4 + h] / s[(size_t)dn * 4 + h];
        float4 f = *(const float4*)(fs + (size_t)sn * HIDN + lane * 4);
        f.x *= a; f.y *= a; f.z *= a; f.w *= a;
        redAdd4(out + (size_t)dn * HIDN + lane * 4, f);
    }
}

// ---------------- node epilogue: h = elu(rst + bc) ----------------
__global__ void node_epi(float* __restrict__ h, const float* __restrict__ bc, int N)
{
    int i = blockIdx.x * blockDim.x + threadIdx.x;
    int total = N * HIDN;
    if (i >= total) return;
    float v = h[i] + bc[i & (HIDN - 1)];
    h[i] = v > 0.0f ? v : expm1f(v);
}

// ---------------- host orchestration ----------------
static inline int cdiv(int a, int b) { return (a + b - 1) / b; }

extern "C" void kernel_launch(void* const* d_in, const int* in_sizes, int n_in,
                              void* d_out, int out_size)
{
    (void)in_sizes; (void)n_in; (void)out_size;
    const float* x_user   = (const float*)d_in[0];
    const float* x_device = (const float*)d_in[1];
    const float* x_ip     = (const float*)d_in[2];
    const float* x_phone  = (const float*)d_in[3];
    const int* eidx[8];
    for (int i = 0; i < 8; i++) eidx[i] = (const int*)d_in[4 + i];

    const float* Wp_user   = (const float*)d_in[12]; const float* bp_user   = (const float*)d_in[13];
    const float* Wp_device = (const float*)d_in[14]; const float* bp_device = (const float*)d_in[15];
    const float* Wp_ip     = (const float*)d_in[16]; const float* bp_ip     = (const float*)d_in[17];
    const float* Wp_phone  = (const float*)d_in[18]; const float* bp_phone  = (const float*)d_in[19];
    const float* Wh1 = (const float*)d_in[28]; const float* bh1 = (const float*)d_in[29];
    const float* Wh2 = (const float*)d_in[30]; const float* bh2 = (const float*)d_in[31];

    void* p;
    cudaGetSymbolAddress(&p, g_hu); float* hu[2] = {(float*)p, (float*)p + (size_t)NU_ * HIDN};
    cudaGetSymbolAddress(&p, g_hd); float* hd[2] = {(float*)p, (float*)p + (size_t)ND_ * HIDN};
    cudaGetSymbolAddress(&p, g_hi); float* hi[2] = {(float*)p, (float*)p + (size_t)NI_ * HIDN};
    cudaGetSymbolAddress(&p, g_hp); float* hp[2] = {(float*)p, (float*)p + (size_t)NP_ * HIDN};
    cudaGetSymbolAddress(&p, g_fs);  float* fs  = (float*)p;
    cudaGetSymbolAddress(&p, g_el);  float* el  = (float*)p;
    cudaGetSymbolAddress(&p, g_er);  float* er  = (float*)p;
    cudaGetSymbolAddress(&p, g_eb);  float* eb  = (float*)p;
    cudaGetSymbolAddress(&p, g_m);   float* mbuf = (float*)p;
    cudaGetSymbolAddress(&p, g_s);   float* sbuf = (float*)p;
    cudaGetSymbolAddress(&p, g_wal); float* wal = (float*)p;
    cudaGetSymbolAddress(&p, g_war); float* war = (float*)p;

    // input projections -> buffer 0
    gemm128<<<cdiv(NU_, 64), 256>>>(x_user,   Wp_user,   bp_user,   hu[0], NU_, 128, 0);
    gemm128<<<cdiv(ND_, 64), 256>>>(x_device, Wp_device, bp_device, hd[0], ND_, 64, 0);
    gemm128<<<cdiv(NI_, 64), 256>>>(x_ip,     Wp_ip,     bp_ip,     hi[0], NI_, 64, 0);
    gemm128<<<cdiv(NP_, 64), 256>>>(x_phone,  Wp_phone,  bp_phone,  hp[0], NP_, 64, 0);

    for (int L = 0; L < 2; L++) {
        const float* Wc = (const float*)d_in[20 + L * 4];
        const float* al = (const float*)d_in[21 + L * 4];
        const float* ar = (const float*)d_in[22 + L * 4];
        const float* bc = (const float*)d_in[23 + L * 4];
        int in_b = L & 1, out_b = in_b ^ 1;

        // relation tables: 0: u->d, 1: d->u, 2: u->i, 3: u->p
        const float* hsrc[4] = {hu[in_b], hd[in_b], hu[in_b], hu[in_b]};
        const float* hdst[4] = {hd[in_b], hu[in_b], hi[in_b], hp[in_b]};
        float* hout[4]       = {hd[out_b], hu[out_b], hi[out_b], hp[out_b]};
        const int Nsrc[4] = {NU_, ND_, NU_, NU_};
        const int Ndst[4] = {ND_, NU_, NI_, NP_};

        for (int r = 0; r < 4; r++) {
            const float* W  = Wc + (size_t)r * 128 * 128;
            const int* srcA = eidx[2 * r + 0];
            const int* dstA = eidx[2 * r + 1];

            prep_attn_w<<<1, 128>>>(W, al + r * 128, ar + r * 128, wal, war);
            gemm128<<<cdiv(Nsrc[r], 64), 256>>>(hsrc[r], W, nullptr, fs, Nsrc[r], 128, 0);
            rowdot<<<cdiv(Nsrc[r], 8), 256>>>(hsrc[r], wal, nullptr, el, Nsrc[r], 4);
            rowdot<<<cdiv(Ndst[r], 8), 256>>>(hdst[r], war, nullptr, er, Ndst[r], 4);

            cudaMemsetAsync(hout[r], 0, (size_t)Ndst[r] * HIDN * sizeof(float));
            cudaMemsetAsync(sbuf, 0, (size_t)Ndst[r] * 4 * sizeof(float));
            init_neg_inf<<<cdiv(Ndst[r] * 4, 256), 256>>>(mbuf, Ndst[r] * 4);

            edge_max_k<<<cdiv(E_, 256), 256>>>(srcA, dstA, el, er, eb, mbuf, E_);
            fix_m<<<cdiv(Ndst[r] * 4, 256), 256>>>(mbuf, Ndst[r] * 4);
            edge_exp_k<<<cdiv(E_, 256), 256>>>(dstA, eb, mbuf, sbuf, E_);
            edge_msg_k<<<cdiv(E_ * 32, 256), 256>>>(srcA, dstA, eb, sbuf, fs, hout[r], E_);
            node_epi<<<cdiv(Ndst[r] * HIDN, 256), 256>>>(hout[r], bc + r * 128, Ndst[r]);
        }
    }

    // head: logits = relu(hu @ Wh1 + bh1) @ Wh2 + bh2   (final user states are in buffer 0)
    gemm128<<<cdiv(NU_, 64), 256>>>(hu[0], Wh1, bh1, fs, NU_, 128, 1);
    rowdot<<<cdiv(NU_, 8), 256>>>(fs, Wh2, bh2, (float*)d_out, NU_, 2);
}

// round 2
// speedup vs baseline: 1.4995x; 1.4995x over previous
#include <cuda_runtime.h>
#include <math.h>
#include <stdint.h>

#define NU_ 100000
#define ND_ 150000
#define NI_ 120000
#define NP_ 80000
#define E_  500000
#define HIDN 128

// ---------------- scratch (static device globals; no allocation) ----------------
__device__ float g_hu[2][(size_t)NU_ * HIDN];
__device__ float g_hd[2][(size_t)ND_ * HIDN];
__device__ float g_hi[2][(size_t)NI_ * HIDN];
__device__ float g_hp[2][(size_t)NP_ * HIDN];
__device__ float g_fs[(size_t)ND_ * HIDN];   // max src-count = ND
__device__ float g_el[ND_ * 4];
__device__ float g_er[ND_ * 4];
__device__ float g_eb[E_ * 4];
__device__ float g_wal[4 * 128 * 4];
__device__ float g_war[4 * 128 * 4];
// CSR scratch (4 relations)
__device__ int g_rowptr[4 * ND_];
__device__ int g_deg[4 * ND_];
__device__ int g_csrsrc[4 * E_];
__device__ int g_cursor[ND_];
__device__ int g_bsum[256];

__device__ __forceinline__ float lrelu(float x) { return x > 0.0f ? x : 0.2f * x; }

// ---------------- GEMM v2: C[N,128] = A[N,K] @ B[K,128] (+bias)(+relu) ----------------
// 128x128 block tile, BK=32, 256 threads, 8x8 microtile.
__global__ __launch_bounds__(256) void gemm_v2(
    const float* __restrict__ A, const float* __restrict__ B,
    const float* __restrict__ bias, float* __restrict__ C,
    int N, int K, int act)
{
    __shared__ float As[32][129];  // [k][row], pad to kill transpose-store conflicts
    __shared__ float Bs[32][128];  // [k][col]
    const int tid = threadIdx.x;
    const int tx = tid & 15;        // col group (8 cols)
    const int ty = tid >> 4;        // row group (8 rows)
    const int row0 = blockIdx.x * 128;

    float acc[8][8];
#pragma unroll
    for (int i = 0; i < 8; i++)
#pragma unroll
        for (int j = 0; j < 8; j++) acc[i][j] = 0.0f;

    for (int kk = 0; kk < K; kk += 32) {
        // A tile: 128 rows x 32 k = 1024 float4, 4 per thread (transposed store)
#pragma unroll
        for (int l = 0; l < 4; l++) {
            int f = tid + l * 256;
            int r = f >> 3;
            int c4 = (f & 7) * 4;
            int gr = row0 + r;
            float4 v = make_float4(0.f, 0.f, 0.f, 0.f);
            if (gr < N) v = *(const float4*)(A + (size_t)gr * K + kk + c4);
            As[c4 + 0][r] = v.x; As[c4 + 1][r] = v.y;
            As[c4 + 2][r] = v.z; As[c4 + 3][r] = v.w;
        }
        // B tile: 32 k x 128 cols = 1024 float4, 4 per thread
#pragma unroll
        for (int l = 0; l < 4; l++) {
            int f = tid + l * 256;
            int r = f >> 5;
            int c4 = (f & 31) * 4;
            *(float4*)&Bs[r][c4] = *(const float4*)(B + (size_t)(kk + r) * HIDN + c4);
        }
        __syncthreads();
#pragma unroll 8
        for (int k = 0; k < 32; k++) {
            float a[8], b[8];
#pragma unroll
            for (int i = 0; i < 8; i++) a[i] = As[k][ty * 8 + i];
            float4 b0 = *(float4*)&Bs[k][tx * 8];
            float4 b1 = *(float4*)&Bs[k][tx * 8 + 4];
            b[0] = b0.x; b[1] = b0.y; b[2] = b0.z; b[3] = b0.w;
            b[4] = b1.x; b[5] = b1.y; b[6] = b1.z; b[7] = b1.w;
#pragma unroll
            for (int i = 0; i < 8; i++)
#pragma unroll
                for (int j = 0; j < 8; j++) acc[i][j] += a[i] * b[j];
        }
        __syncthreads();
    }

    float4 bia0 = make_float4(0.f, 0.f, 0.f, 0.f), bia1 = bia0;
    if (bias) {
        bia0 = *(const float4*)(bias + tx * 8);
        bia1 = *(const float4*)(bias + tx * 8 + 4);
    }
#pragma unroll
    for (int i = 0; i < 8; i++) {
        int r = row0 + ty * 8 + i;
        if (r < N) {
            float4 o0 = make_float4(acc[i][0] + bia0.x, acc[i][1] + bia0.y,
                                    acc[i][2] + bia0.z, acc[i][3] + bia0.w);
            float4 o1 = make_float4(acc[i][4] + bia1.x, acc[i][5] + bia1.y,
                                    acc[i][6] + bia1.z, acc[i][7] + bia1.w);
            if (act == 1) {
                o0.x = fmaxf(o0.x, 0.f); o0.y = fmaxf(o0.y, 0.f);
                o0.z = fmaxf(o0.z, 0.f); o0.w = fmaxf(o0.w, 0.f);
                o1.x = fmaxf(o1.x, 0.f); o1.y = fmaxf(o1.y, 0.f);
                o1.z = fmaxf(o1.z, 0.f); o1.w = fmaxf(o1.w, 0.f);
            }
            *(float4*)(C + (size_t)r * HIDN + tx * 8) = o0;
            *(float4*)(C + (size_t)r * HIDN + tx * 8 + 4) = o1;
        }
    }
}

// ---------------- narrow GEMM: out[N,NOUT] = H[N,128] @ w[128,NOUT] (+bias), NOUT<=4 ----------------
__global__ void rowdot(const float* __restrict__ Hm, const float* __restrict__ w,
                       const float* __restrict__ bias, float* __restrict__ out,
                       int N, int NOUT)
{
    __shared__ float ws[128 * 4];
    for (int i = threadIdx.x; i < 128 * NOUT; i += blockDim.x) ws[i] = w[i];
    __syncthreads();
    int gwarp = (blockIdx.x * blockDim.x + threadIdx.x) >> 5;
    int lane = threadIdx.x & 31;
    if (gwarp >= N) return;
    int row = gwarp;
    float4 h = *(const float4*)(Hm + (size_t)row * HIDN + lane * 4);
    float acc[4] = {0.f, 0.f, 0.f, 0.f};
    const float hv[4] = {h.x, h.y, h.z, h.w};
#pragma unroll
    for (int q = 0; q < 4; q++) {
        int k = lane * 4 + q;
        for (int o = 0; o < NOUT; o++) acc[o] += hv[q] * ws[k * NOUT + o];
    }
#pragma unroll
    for (int off = 16; off; off >>= 1)
        for (int o = 0; o < 4; o++) acc[o] += __shfl_down_sync(0xffffffffu, acc[o], off);
    if (lane == 0)
        for (int o = 0; o < NOUT; o++)
            out[(size_t)row * NOUT + o] = acc[o] + (bias ? bias[o] : 0.0f);
}

// ---------------- fold attention vectors into W for all 4 relations ----------------
__global__ void prep_attn_w4(const float* __restrict__ Wc, const float* __restrict__ al,
                             const float* __restrict__ ar,
                             float* __restrict__ wal, float* __restrict__ war)
{
    int r = blockIdx.x;
    int k = threadIdx.x;  // 128
    const float* W = Wc + (size_t)r * 128 * 128;
    const float* alr = al + r * 128;
    const float* arr = ar + r * 128;
#pragma unroll
    for (int h = 0; h < 4; h++) {
        float sl = 0.f, sr = 0.f;
#pragma unroll
        for (int d = 0; d < 32; d++) {
            float wv = W[k * 128 + h * 32 + d];
            sl += wv * alr[h * 32 + d];
            sr += wv * arr[h * 32 + d];
        }
        wal[r * 512 + k * 4 + h] = sl;
        war[r * 512 + k * 4 + h] = sr;
    }
}

// ---------------- CSR build: histogram / scan / scatter ----------------
__global__ void hist_k(const int* __restrict__ dst, int* __restrict__ cnt, int E) {
    int e = blockIdx.x * blockDim.x + threadIdx.x;
    if (e < E) atomicAdd(&cnt[dst[e]], 1);
}

#define SCAN_T 256
#define SCAN_E 8
__global__ void scan1_k(const int* __restrict__ in, int* __restrict__ out,
                        int* __restrict__ bsum, int n)
{
    __shared__ int sm[SCAN_T];
    int base = blockIdx.x * SCAN_T * SCAN_E + threadIdx.x * SCAN_E;
    int v[SCAN_E];
    int s = 0;
#pragma unroll
    for (int i = 0; i < SCAN_E; i++) {
        v[i] = (base + i < n) ? in[base + i] : 0;
        s += v[i];
    }
    sm[threadIdx.x] = s;
    __syncthreads();
    for (int off = 1; off < SCAN_T; off <<= 1) {
        int t = (threadIdx.x >= off) ? sm[threadIdx.x - off] : 0;
        __syncthreads();
        sm[threadIdx.x] += t;
        __syncthreads();
    }
    int run = sm[threadIdx.x] - s;  // exclusive prefix for this thread
#pragma unroll
    for (int i = 0; i < SCAN_E; i++) {
        if (base + i < n) out[base + i] = run;
        run += v[i];
    }
    if (threadIdx.x == SCAN_T - 1) bsum[blockIdx.x] = sm[SCAN_T - 1];
}

__global__ void scan2_k(int* __restrict__ bsum, int nb) {
    __shared__ int sm[256];
    int v = (threadIdx.x < nb) ? bsum[threadIdx.x] : 0;
    sm[threadIdx.x] = v;
    __syncthreads();
    for (int off = 1; off < 256; off <<= 1) {
        int t = (threadIdx.x >= off) ? sm[threadIdx.x - off] : 0;
        __syncthreads();
        sm[threadIdx.x] += t;
        __syncthreads();
    }
    if (threadIdx.x < nb) bsum[threadIdx.x] = sm[threadIdx.x] - v;  // exclusive
}

__global__ void scan3_k(int* __restrict__ out, const int* __restrict__ bsum, int n) {
    int i = blockIdx.x * blockDim.x + threadIdx.x;
    if (i < n) out[i] += bsum[i / (SCAN_T * SCAN_E)];
}

__global__ void scatter_k(const int* __restrict__ src, const int* __restrict__ dst,
                          int* __restrict__ cursor, int* __restrict__ csr_src, int E)
{
    int e = blockIdx.x * blockDim.x + threadIdx.x;
    if (e >= E) return;
    int dn = dst[e];
    int pos = atomicAdd(&cursor[dn], 1);
    csr_src[pos] = src[e];
}

// ---------------- attention stats: thread per dst, online softmax, normalize in place ----------------
__global__ void attn_stats(const int* __restrict__ rowptr, const int* __restrict__ deg,
                           const int* __restrict__ csr_src, const float* __restrict__ el,
                           const float* __restrict__ er, float* __restrict__ eb, int Nd)
{
    int d = blockIdx.x * blockDim.x + threadIdx.x;
    if (d >= Nd) return;
    int dg = deg[d];
    if (dg == 0) return;
    int st = rowptr[d];
    float4 r4 = *(const float4*)(er + (size_t)d * 4);
    float m[4] = {-INFINITY, -INFINITY, -INFINITY, -INFINITY};
    float s[4] = {0.f, 0.f, 0.f, 0.f};
    for (int j = 0; j < dg; j++) {
        int sn = csr_src[st + j];
        float4 l4 = *(const float4*)(el + (size_t)sn * 4);
        float e[4];
        e[0] = lrelu(l4.x + r4.x); e[1] = lrelu(l4.y + r4.y);
        e[2] = lrelu(l4.z + r4.z); e[3] = lrelu(l4.w + r4.w);
        *(float4*)(eb + (size_t)(st + j) * 4) = make_float4(e[0], e[1], e[2], e[3]);
#pragma unroll
        for (int h = 0; h < 4; h++) {
            if (e[h] > m[h]) { s[h] = s[h] * __expf(m[h] - e[h]) + 1.0f; m[h] = e[h]; }
            else             { s[h] += __expf(e[h] - m[h]); }
        }
    }
    float inv[4];
#pragma unroll
    for (int h = 0; h < 4; h++) inv[h] = 1.0f / s[h];
    for (int j = 0; j < dg; j++) {
        float4 v = *(float4*)(eb + (size_t)(st + j) * 4);
        v.x = __expf(v.x - m[0]) * inv[0];
        v.y = __expf(v.y - m[1]) * inv[1];
        v.z = __expf(v.z - m[2]) * inv[2];
        v.w = __expf(v.w - m[3]) * inv[3];
        *(float4*)(eb + (size_t)(st + j) * 4) = v;
    }
}

// ---------------- aggregate: warp per dst, register accumulation, fused bias+ELU ----------------
__global__ void attn_aggr(const int* __restrict__ rowptr, const int* __restrict__ deg,
                          const int* __restrict__ csr_src, const float* __restrict__ eb,
                          const float* __restrict__ fs, const float* __restrict__ bc,
                          float* __restrict__ out, int Nd)
{
    int gid = blockIdx.x * blockDim.x + threadIdx.x;
    int w = gid >> 5, l = gid & 31;
    if (w >= Nd) return;
    int st = rowptr[w], dg = deg[w];
    int h = l >> 3;
    float4 acc = make_float4(0.f, 0.f, 0.f, 0.f);
    for (int j = 0; j < dg; j++) {
        int sn = __ldg(&csr_src[st + j]);
        float a = __ldg(&eb[(size_t)(st + j) * 4 + h]);
        float4 f = *(const float4*)(fs + (size_t)sn * HIDN + l * 4);
        acc.x += a * f.x; acc.y += a * f.y;
        acc.z += a * f.z; acc.w += a * f.w;
    }
    float4 b4 = *(const float4*)(bc + l * 4);
    acc.x += b4.x; acc.y += b4.y; acc.z += b4.z; acc.w += b4.w;
    acc.x = acc.x > 0.f ? acc.x : expm1f(acc.x);
    acc.y = acc.y > 0.f ? acc.y : expm1f(acc.y);
    acc.z = acc.z > 0.f ? acc.z : expm1f(acc.z);
    acc.w = acc.w > 0.f ? acc.w : expm1f(acc.w);
    *(float4*)(out + (size_t)w * HIDN + l * 4) = acc;
}

// ---------------- host orchestration ----------------
static inline int cdiv(int a, int b) { return (a + b - 1) / b; }

extern "C" void kernel_launch(void* const* d_in, const int* in_sizes, int n_in,
                              void* d_out, int out_size)
{
    (void)in_sizes; (void)n_in; (void)out_size;
    const float* x_user   = (const float*)d_in[0];
    const float* x_device = (const float*)d_in[1];
    const float* x_ip     = (const float*)d_in[2];
    const float* x_phone  = (const float*)d_in[3];
    const int* eidx[8];
    for (int i = 0; i < 8; i++) eidx[i] = (const int*)d_in[4 + i];

    const float* Wp_user   = (const float*)d_in[12]; const float* bp_user   = (const float*)d_in[13];
    const float* Wp_device = (const float*)d_in[14]; const float* bp_device = (const float*)d_in[15];
    const float* Wp_ip     = (const float*)d_in[16]; const float* bp_ip     = (const float*)d_in[17];
    const float* Wp_phone  = (const float*)d_in[18]; const float* bp_phone  = (const float*)d_in[19];
    const float* Wh1 = (const float*)d_in[28]; const float* bh1 = (const float*)d_in[29];
    const float* Wh2 = (const float*)d_in[30]; const float* bh2 = (const float*)d_in[31];

    void* p;
    cudaGetSymbolAddress(&p, g_hu); float* hu[2] = {(float*)p, (float*)p + (size_t)NU_ * HIDN};
    cudaGetSymbolAddress(&p, g_hd); float* hd[2] = {(float*)p, (float*)p + (size_t)ND_ * HIDN};
    cudaGetSymbolAddress(&p, g_hi); float* hi[2] = {(float*)p, (float*)p + (size_t)NI_ * HIDN};
    cudaGetSymbolAddress(&p, g_hp); float* hp[2] = {(float*)p, (float*)p + (size_t)NP_ * HIDN};
    cudaGetSymbolAddress(&p, g_fs);  float* fs  = (float*)p;
    cudaGetSymbolAddress(&p, g_el);  float* el  = (float*)p;
    cudaGetSymbolAddress(&p, g_er);  float* er  = (float*)p;
    cudaGetSymbolAddress(&p, g_eb);  float* eb  = (float*)p;
    cudaGetSymbolAddress(&p, g_wal); float* wal = (float*)p;
    cudaGetSymbolAddress(&p, g_war); float* war = (float*)p;
    cudaGetSymbolAddress(&p, g_rowptr); int* rowptr = (int*)p;
    cudaGetSymbolAddress(&p, g_deg);    int* deg    = (int*)p;
    cudaGetSymbolAddress(&p, g_csrsrc); int* csrsrc = (int*)p;
    cudaGetSymbolAddress(&p, g_cursor); int* cursor = (int*)p;
    cudaGetSymbolAddress(&p, g_bsum);   int* bsum   = (int*)p;

    const int Nsrc[4] = {NU_, ND_, NU_, NU_};
    const int Ndst[4] = {ND_, NU_, NI_, NP_};

    // ---- build CSR for each relation (reused by both layers) ----
    for (int r = 0; r < 4; r++) {
        const int* srcA = eidx[2 * r + 0];
        const int* dstA = eidx[2 * r + 1];
        int nd = Ndst[r];
        int* deg_r = deg + (size_t)r * ND_;
        int* rp_r  = rowptr + (size_t)r * ND_;
        int* cs_r  = csrsrc + (size_t)r * E_;
        cudaMemsetAsync(deg_r, 0, (size_t)nd * sizeof(int));
        hist_k<<<cdiv(E_, 256), 256>>>(dstA, deg_r, E_);
        int nb = cdiv(nd, SCAN_T * SCAN_E);
        scan1_k<<<nb, SCAN_T>>>(deg_r, rp_r, bsum, nd);
        scan2_k<<<1, 256>>>(bsum, nb);
        scan3_k<<<cdiv(nd, 256), 256>>>(rp_r, bsum, nd);
        cudaMemcpyAsync(cursor, rp_r, (size_t)nd * sizeof(int), cudaMemcpyDeviceToDevice);
        scatter_k<<<cdiv(E_, 256), 256>>>(srcA, dstA, cursor, cs_r, E_);
    }

    // ---- input projections -> buffer 0 ----
    gemm_v2<<<cdiv(NU_, 128), 256>>>(x_user,   Wp_user,   bp_user,   hu[0], NU_, 128, 0);
    gemm_v2<<<cdiv(ND_, 128), 256>>>(x_device, Wp_device, bp_device, hd[0], ND_, 64, 0);
    gemm_v2<<<cdiv(NI_, 128), 256>>>(x_ip,     Wp_ip,     bp_ip,     hi[0], NI_, 64, 0);
    gemm_v2<<<cdiv(NP_, 128), 256>>>(x_phone,  Wp_phone,  bp_phone,  hp[0], NP_, 64, 0);

    for (int L = 0; L < 2; L++) {
        const float* Wc = (const float*)d_in[20 + L * 4];
        const float* al = (const float*)d_in[21 + L * 4];
        const float* ar = (const float*)d_in[22 + L * 4];
        const float* bc = (const float*)d_in[23 + L * 4];
        int in_b = L & 1, out_b = in_b ^ 1;

        prep_attn_w4<<<4, 128>>>(Wc, al, ar, wal, war);

        // relation tables: 0: u->d, 1: d->u, 2: u->i, 3: u->p
        const float* hsrc[4] = {hu[in_b], hd[in_b], hu[in_b], hu[in_b]};
        const float* hdst[4] = {hd[in_b], hu[in_b], hi[in_b], hp[in_b]};
        float* hout[4]       = {hd[out_b], hu[out_b], hi[out_b], hp[out_b]};

        for (int r = 0; r < 4; r++) {
            const float* W = Wc + (size_t)r * 128 * 128;
            int* deg_r = deg + (size_t)r * ND_;
            int* rp_r  = rowptr + (size_t)r * ND_;
            int* cs_r  = csrsrc + (size_t)r * E_;

            gemm_v2<<<cdiv(Nsrc[r], 128), 256>>>(hsrc[r], W, nullptr, fs, Nsrc[r], 128, 0);
            rowdot<<<cdiv(Nsrc[r], 8), 256>>>(hsrc[r], wal + r * 512, nullptr, el, Nsrc[r], 4);
            rowdot<<<cdiv(Ndst[r], 8), 256>>>(hdst[r], war + r * 512, nullptr, er, Ndst[r], 4);

            attn_stats<<<cdiv(Ndst[r], 256), 256>>>(rp_r, deg_r, cs_r, el, er, eb, Ndst[r]);
            attn_aggr<<<cdiv(Ndst[r] * 32, 256), 256>>>(rp_r, deg_r, cs_r, eb, fs,
                                                        bc + r * 128, hout[r], Ndst[r]);
        }
    }

    // head: logits = relu(hu @ Wh1 + bh1) @ Wh2 + bh2   (final user states in buffer 0)
    gemm_v2<<<cdiv(NU_, 128), 256>>>(hu[0], Wh1, bh1, fs, NU_, 128, 1);
    rowdot<<<cdiv(NU_, 8), 256>>>(fs, Wh2, bh2, (float*)d_out, NU_, 2);
}

// round 4
// speedup vs baseline: 1.7488x; 1.1662x over previous
#include <cuda_runtime.h>
#include <cuda_bf16.h>
#include <math.h>
#include <stdint.h>

#define NU_ 100000
#define ND_ 150000
#define NI_ 120000
#define NP_ 80000
#define E_  500000
#define HIDN 128

// ---------------- scratch (static device globals; no allocation) ----------------
__device__ float g_hu[2][(size_t)NU_ * HIDN];
__device__ float g_hd[2][(size_t)ND_ * HIDN];
__device__ float g_hi[2][(size_t)NI_ * HIDN];
__device__ float g_hp[2][(size_t)NP_ * HIDN];
__device__ float g_fs[(size_t)ND_ * HIDN];   // max src-count = ND
__device__ float g_el[ND_ * 4];
__device__ float g_er[ND_ * 4];
__device__ float g_eb[E_ * 4];
__device__ float g_wal[4 * 128 * 4];
__device__ float g_war[4 * 128 * 4];
// transposed/split weights: 13 slots x (hi,lo) x 128*128 bf16
__device__ __nv_bfloat16 g_wt[13 * 2 * 16384];
// CSR scratch (4 relations)
__device__ int g_rowptr[4 * ND_];
__device__ int g_deg[4 * ND_];
__device__ int g_csrsrc[4 * E_];
__device__ int g_cursor[ND_];
__device__ int g_bsum[256];

__device__ __forceinline__ float lrelu(float x) { return x > 0.0f ? x : 0.2f * x; }

__device__ __forceinline__ uint32_t smem_u32(const void* p) {
    uint32_t a;
    asm("{ .reg .u64 t; cvta.to.shared.u64 t, %1; cvt.u32.u64 %0, t; }" : "=r"(a) : "l"(p));
    return a;
}

// ================= warp-level MMA helpers (sm_80+, valid on base sm_103) =================
__device__ __forceinline__ void ldm_x4(uint32_t* r, uint32_t addr) {
    asm volatile("ldmatrix.sync.aligned.m8n8.x4.shared.b16 {%0,%1,%2,%3}, [%4];"
                 : "=r"(r[0]), "=r"(r[1]), "=r"(r[2]), "=r"(r[3]) : "r"(addr));
}
__device__ __forceinline__ void mma16816(float* d, const uint32_t* a, const uint32_t* b) {
    asm volatile("mma.sync.aligned.m16n8k16.row.col.f32.bf16.bf16.f32 "
                 "{%0,%1,%2,%3}, {%4,%5,%6,%7}, {%8,%9}, {%0,%1,%2,%3};"
                 : "+f"(d[0]), "+f"(d[1]), "+f"(d[2]), "+f"(d[3])
                 : "r"(a[0]), "r"(a[1]), "r"(a[2]), "r"(a[3]), "r"(b[0]), "r"(b[1]));
}

// ---------------- tensor-core GEMM: C[N,128] = A[N,K] @ W[K,128] (+bias)(+relu) ----------------
// A fp32 row-major; W pre-split/transposed: Bhi/Blo bf16 [128(n), K] row-major.
// 256 threads, 128x128 CTA tile, 8 warps of 32m x 64n, BK=64, split-bf16 3-MMA.
// SMEM rows padded to 72 bf16 (144B) -> ldmatrix phases are bank-conflict-free.
#define SA 72
#define TILE_B (128 * SA * 2)   // 18432 bytes per tile
__global__ __launch_bounds__(256) void gemm_mma(
    const float* __restrict__ A, const __nv_bfloat16* __restrict__ Bhi,
    const __nv_bfloat16* __restrict__ Blo, const float* __restrict__ bias,
    float* __restrict__ C, int Nrows, int K, int act)
{
    extern __shared__ char sm[];
    char* p_ahi = sm;
    char* p_alo = sm + TILE_B;
    char* p_bhi = sm + 2 * TILE_B;
    char* p_blo = sm + 3 * TILE_B;
    const uint32_t s_ahi = smem_u32(p_ahi);
    const uint32_t s_alo = smem_u32(p_alo);
    const uint32_t s_bhi = smem_u32(p_bhi);
    const uint32_t s_blo = smem_u32(p_blo);

    const int tid = threadIdx.x;
    const int wid = tid >> 5;
    const int lane = tid & 31;
    const int warp_m = wid & 3;       // 4 row-groups of 32
    const int warp_n = wid >> 2;      // 2 col-groups of 64
    const int row0 = blockIdx.x * 128;

    float acc[2][8][4];
#pragma unroll
    for (int m = 0; m < 2; m++)
#pragma unroll
        for (int n = 0; n < 8; n++)
#pragma unroll
            for (int q = 0; q < 4; q++) acc[m][n][q] = 0.0f;

    const int nchunk = K >> 6;
    for (int kc = 0; kc < nchunk; kc++) {
        // ---- load A chunk (128 rows x 64 cols fp32), split -> bf16 hi/lo ----
#pragma unroll
        for (int it = 0; it < 8; it++) {
            int idx = tid + it * 256;            // 0..2047
            int row = idx >> 4;
            int k4 = (idx & 15) << 2;
            int gr = row0 + row;
            float4 v = make_float4(0.f, 0.f, 0.f, 0.f);
            if (gr < Nrows) v = *(const float4*)(A + (size_t)gr * K + kc * 64 + k4);
            __nv_bfloat162 h01 = __floats2bfloat162_rn(v.x, v.y);
            __nv_bfloat162 h23 = __floats2bfloat162_rn(v.z, v.w);
            __nv_bfloat162 l01 = __floats2bfloat162_rn(v.x - __bfloat162float(h01.x),
                                                       v.y - __bfloat162float(h01.y));
            __nv_bfloat162 l23 = __floats2bfloat162_rn(v.z - __bfloat162float(h23.x),
                                                       v.w - __bfloat162float(h23.y));
            uint32_t off = (uint32_t)row * (SA * 2) + (uint32_t)k4 * 2;
            *(__nv_bfloat162*)(p_ahi + off) = h01;
            *(__nv_bfloat162*)(p_ahi + off + 4) = h23;
            *(__nv_bfloat162*)(p_alo + off) = l01;
            *(__nv_bfloat162*)(p_alo + off + 4) = l23;
        }
        // ---- load B chunk (128 n-rows x 64 k), bf16 hi/lo from global ----
#pragma unroll
        for (int it = 0; it < 8; it++) {
            int idx = tid + it * 256;
            int row = idx >> 4;
            int k4 = (idx & 15) << 2;
            uint2 vh = *(const uint2*)(Bhi + (size_t)row * K + kc * 64 + k4);
            uint2 vl = *(const uint2*)(Blo + (size_t)row * K + kc * 64 + k4);
            uint32_t off = (uint32_t)row * (SA * 2) + (uint32_t)k4 * 2;
            *(uint2*)(p_bhi + off) = vh;
            *(uint2*)(p_blo + off) = vl;
        }
        __syncthreads();

        // ---- 4 k-steps of 16 ----
#pragma unroll
        for (int ks = 0; ks < 4; ks++) {
            const int k0 = ks * 16;
            // A fragments: 2 m-tiles, hi+lo
            uint32_t ah[2][4], al[2][4];
#pragma unroll
            for (int mt = 0; mt < 2; mt++) {
                int r = warp_m * 32 + mt * 16 + (lane & 7) + ((lane >> 3) & 1) * 8;
                int c = k0 + (lane >> 4) * 8;
                uint32_t off = (uint32_t)r * (SA * 2) + (uint32_t)c * 2;
                ldm_x4(ah[mt], s_ahi + off);
                ldm_x4(al[mt], s_alo + off);
            }
            // B fragments: 4 n-tile pairs, hi+lo
            uint32_t bh[4][4], bl[4][4];
#pragma unroll
            for (int pp = 0; pp < 4; pp++) {
                int r = warp_n * 64 + pp * 16 + (lane & 7) + (lane >= 16 ? 8 : 0);
                int c = k0 + ((lane >> 3) & 1) * 8;
                uint32_t off = (uint32_t)r * (SA * 2) + (uint32_t)c * 2;
                ldm_x4(bh[pp], s_bhi + off);
                ldm_x4(bl[pp], s_blo + off);
            }
#pragma unroll
            for (int mt = 0; mt < 2; mt++)
#pragma unroll
                for (int pp = 0; pp < 4; pp++)
#pragma unroll
                    for (int hh = 0; hh < 2; hh++) {
                        float* d = acc[mt][pp * 2 + hh];
                        mma16816(d, ah[mt], &bh[pp][hh * 2]);
                        mma16816(d, ah[mt], &bl[pp][hh * 2]);
                        mma16816(d, al[mt], &bh[pp][hh * 2]);
                    }
        }
        __syncthreads();
    }

    // ---- epilogue ----
#pragma unroll
    for (int mt = 0; mt < 2; mt++) {
        int rbase = row0 + warp_m * 32 + mt * 16 + (lane >> 2);
#pragma unroll
        for (int nt = 0; nt < 8; nt++) {
            int col = warp_n * 64 + nt * 8 + (lane & 3) * 2;
            float2 b2 = make_float2(0.f, 0.f);
            if (bias) b2 = *(const float2*)(bias + col);
            float2 o0 = make_float2(acc[mt][nt][0] + b2.x, acc[mt][nt][1] + b2.y);
            float2 o1 = make_float2(acc[mt][nt][2] + b2.x, acc[mt][nt][3] + b2.y);
            if (act == 1) {
                o0.x = fmaxf(o0.x, 0.f); o0.y = fmaxf(o0.y, 0.f);
                o1.x = fmaxf(o1.x, 0.f); o1.y = fmaxf(o1.y, 0.f);
            }
            if (rbase < Nrows)     *(float2*)(C + (size_t)rbase * HIDN + col) = o0;
            if (rbase + 8 < Nrows) *(float2*)(C + (size_t)(rbase + 8) * HIDN + col) = o1;
        }
    }
}

// ---------------- weight prep: W[K,128] fp32 -> hi/lo bf16 [128,K] (transposed) ----------------
__global__ void convert_w(const float* __restrict__ W, __nv_bfloat16* __restrict__ hi,
                          __nv_bfloat16* __restrict__ lo, int K)
{
    int i = blockIdx.x * blockDim.x + threadIdx.x;
    if (i >= 128 * K) return;
    int n = i / K, k = i - n * K;
    float v = W[(size_t)k * 128 + n];
    __nv_bfloat16 h = __float2bfloat16(v);
    hi[i] = h;
    lo[i] = __float2bfloat16(v - __bfloat162float(h));
}

// ---------------- narrow GEMM: out[N,NOUT] = H[N,128] @ w[128,NOUT] (+bias), NOUT<=4 ----------------
__global__ void rowdot(const float* __restrict__ Hm, const float* __restrict__ w,
                       const float* __restrict__ bias, float* __restrict__ out,
                       int N, int NOUT)
{
    __shared__ float ws[128 * 4];
    for (int i = threadIdx.x; i < 128 * NOUT; i += blockDim.x) ws[i] = w[i];
    __syncthreads();
    int gwarp = (blockIdx.x * blockDim.x + threadIdx.x) >> 5;
    int lane = threadIdx.x & 31;
    if (gwarp >= N) return;
    int row = gwarp;
    float4 h = *(const float4*)(Hm + (size_t)row * HIDN + lane * 4);
    float acc[4] = {0.f, 0.f, 0.f, 0.f};
    const float hv[4] = {h.x, h.y, h.z, h.w};
#pragma unroll
    for (int q = 0; q < 4; q++) {
        int k = lane * 4 + q;
        for (int o = 0; o < NOUT; o++) acc[o] += hv[q] * ws[k * NOUT + o];
    }
#pragma unroll
    for (int off = 16; off; off >>= 1)
        for (int o = 0; o < 4; o++) acc[o] += __shfl_down_sync(0xffffffffu, acc[o], off);
    if (lane == 0)
        for (int o = 0; o < NOUT; o++)
            out[(size_t)row * NOUT + o] = acc[o] + (bias ? bias[o] : 0.0f);
}

// ---------------- fold attention vectors into W for all 4 relations ----------------
__global__ void prep_attn_w4(const float* __restrict__ Wc, const float* __restrict__ al,
                             const float* __restrict__ ar,
                             float* __restrict__ wal, float* __restrict__ war)
{
    int r = blockIdx.x;
    int k = threadIdx.x;  // 128
    const float* W = Wc + (size_t)r * 128 * 128;
    const float* alr = al + r * 128;
    const float* arr = ar + r * 128;
#pragma unroll
    for (int h = 0; h < 4; h++) {
        float sl = 0.f, sr = 0.f;
#pragma unroll
        for (int d = 0; d < 32; d++) {
            float wv = W[k * 128 + h * 32 + d];
            sl += wv * alr[h * 32 + d];
            sr += wv * arr[h * 32 + d];
        }
        wal[r * 512 + k * 4 + h] = sl;
        war[r * 512 + k * 4 + h] = sr;
    }
}

// ---------------- CSR build: histogram / scan / scatter ----------------
__global__ void hist_k(const int* __restrict__ dst, int* __restrict__ cnt, int E) {
    int e = blockIdx.x * blockDim.x + threadIdx.x;
    if (e < E) atomicAdd(&cnt[dst[e]], 1);
}

#define SCAN_T 256
#define SCAN_E 8
__global__ void scan1_k(const int* __restrict__ in, int* __restrict__ out,
                        int* __restrict__ bsum, int n)
{
    __shared__ int sm[SCAN_T];
    int base = blockIdx.x * SCAN_T * SCAN_E + threadIdx.x * SCAN_E;
    int v[SCAN_E];
    int s = 0;
#pragma unroll
    for (int i = 0; i < SCAN_E; i++) {
        v[i] = (base + i < n) ? in[base + i] : 0;
        s += v[i];
    }
    sm[threadIdx.x] = s;
    __syncthreads();
    for (int off = 1; off < SCAN_T; off <<= 1) {
        int t = (threadIdx.x >= off) ? sm[threadIdx.x - off] : 0;
        __syncthreads();
        sm[threadIdx.x] += t;
        __syncthreads();
    }
    int run = sm[threadIdx.x] - s;
#pragma unroll
    for (int i = 0; i < SCAN_E; i++) {
        if (base + i < n) out[base + i] = run;
        run += v[i];
    }
    if (threadIdx.x == SCAN_T - 1) bsum[blockIdx.x] = sm[SCAN_T - 1];
}

__global__ void scan2_k(int* __restrict__ bsum, int nb) {
    __shared__ int sm[256];
    int v = (threadIdx.x < nb) ? bsum[threadIdx.x] : 0;
    sm[threadIdx.x] = v;
    __syncthreads();
    for (int off = 1; off < 256; off <<= 1) {
        int t = (threadIdx.x >= off) ? sm[threadIdx.x - off] : 0;
        __syncthreads();
        sm[threadIdx.x] += t;
        __syncthreads();
    }
    if (threadIdx.x < nb) bsum[threadIdx.x] = sm[threadIdx.x] - v;
}

__global__ void scan3_k(int* __restrict__ out, const int* __restrict__ bsum, int n) {
    int i = blockIdx.x * blockDim.x + threadIdx.x;
    if (i < n) out[i] += bsum[i / (SCAN_T * SCAN_E)];
}

__global__ void scatter_k(const int* __restrict__ src, const int* __restrict__ dst,
                          int* __restrict__ cursor, int* __restrict__ csr_src, int E)
{
    int e = blockIdx.x * blockDim.x + threadIdx.x;
    if (e >= E) return;
    int dn = dst[e];
    int pos = atomicAdd(&cursor[dn], 1);
    csr_src[pos] = src[e];
}

// ---------------- attention stats: thread per dst, online softmax, normalize in place ----------------
__global__ void attn_stats(const int* __restrict__ rowptr, const int* __restrict__ deg,
                           const int* __restrict__ csr_src, const float* __restrict__ el,
                           const float* __restrict__ er, float* __restrict__ eb, int Nd)
{
    int d = blockIdx.x * blockDim.x + threadIdx.x;
    if (d >= Nd) return;
    int dg = deg[d];
    if (dg == 0) return;
    int st = rowptr[d];
    float4 r4 = *(const float4*)(er + (size_t)d * 4);
    float m[4] = {-INFINITY, -INFINITY, -INFINITY, -INFINITY};
    float s[4] = {0.f, 0.f, 0.f, 0.f};
    for (int j = 0; j < dg; j++) {
        int sn = csr_src[st + j];
        float4 l4 = *(const float4*)(el + (size_t)sn * 4);
        float e[4];
        e[0] = lrelu(l4.x + r4.x); e[1] = lrelu(l4.y + r4.y);
        e[2] = lrelu(l4.z + r4.z); e[3] = lrelu(l4.w + r4.w);
        *(float4*)(eb + (size_t)(st + j) * 4) = make_float4(e[0], e[1], e[2], e[3]);
#pragma unroll
        for (int h = 0; h < 4; h++) {
            if (e[h] > m[h]) { s[h] = s[h] * __expf(m[h] - e[h]) + 1.0f; m[h] = e[h]; }
            else             { s[h] += __expf(e[h] - m[h]); }
        }
    }
    float inv[4];
#pragma unroll
    for (int h = 0; h < 4; h++) inv[h] = 1.0f / s[h];
    for (int j = 0; j < dg; j++) {
        float4 v = *(float4*)(eb + (size_t)(st + j) * 4);
        v.x = __expf(v.x - m[0]) * inv[0];
        v.y = __expf(v.y - m[1]) * inv[1];
        v.z = __expf(v.z - m[2]) * inv[2];
        v.w = __expf(v.w - m[3]) * inv[3];
        *(float4*)(eb + (size_t)(st + j) * 4) = v;
    }
}

// ---------------- aggregate: warp per dst, register accumulation, fused bias+ELU ----------------
__global__ void attn_aggr(const int* __restrict__ rowptr, const int* __restrict__ deg,
                          const int* __restrict__ csr_src, const float* __restrict__ eb,
                          const float* __restrict__ fs, const float* __restrict__ bc,
                          float* __restrict__ out, int Nd)
{
    int gid = blockIdx.x * blockDim.x + threadIdx.x;
    int w = gid >> 5, l = gid & 31;
    if (w >= Nd) return;
    int st = rowptr[w], dg = deg[w];
    int h = l >> 3;
    float4 acc = make_float4(0.f, 0.f, 0.f, 0.f);
    for (int j = 0; j < dg; j++) {
        int sn = __ldg(&csr_src[st + j]);
        float a = __ldg(&eb[(size_t)(st + j) * 4 + h]);
        float4 f = *(const float4*)(fs + (size_t)sn * HIDN + l * 4);
        acc.x += a * f.x; acc.y += a * f.y;
        acc.z += a * f.z; acc.w += a * f.w;
    }
    float4 b4 = *(const float4*)(bc + l * 4);
    acc.x += b4.x; acc.y += b4.y; acc.z += b4.z; acc.w += b4.w;
    acc.x = acc.x > 0.f ? acc.x : expm1f(acc.x);
    acc.y = acc.y > 0.f ? acc.y : expm1f(acc.y);
    acc.z = acc.z > 0.f ? acc.z : expm1f(acc.z);
    acc.w = acc.w > 0.f ? acc.w : expm1f(acc.w);
    *(float4*)(out + (size_t)w * HIDN + l * 4) = acc;
}

// ---------------- host orchestration ----------------
static inline int cdiv(int a, int b) { return (a + b - 1) / b; }

extern "C" void kernel_launch(void* const* d_in, const int* in_sizes, int n_in,
                              void* d_out, int out_size)
{
    (void)in_sizes; (void)n_in; (void)out_size;
    const float* x_user   = (const float*)d_in[0];
    const float* x_device = (const float*)d_in[1];
    const float* x_ip     = (const float*)d_in[2];
    const float* x_phone  = (const float*)d_in[3];
    const int* eidx[8];
    for (int i = 0; i < 8; i++) eidx[i] = (const int*)d_in[4 + i];

    const float* Wp[4]  = {(const float*)d_in[12], (const float*)d_in[14],
                           (const float*)d_in[16], (const float*)d_in[18]};
    const float* bpv[4] = {(const float*)d_in[13], (const float*)d_in[15],
                           (const float*)d_in[17], (const float*)d_in[19]};
    const float* Wh1 = (const float*)d_in[28]; const float* bh1 = (const float*)d_in[29];
    const float* Wh2 = (const float*)d_in[30]; const float* bh2 = (const float*)d_in[31];

    void* p;
    cudaGetSymbolAddress(&p, g_hu); float* hu[2] = {(float*)p, (float*)p + (size_t)NU_ * HIDN};
    cudaGetSymbolAddress(&p, g_hd); float* hd[2] = {(float*)p, (float*)p + (size_t)ND_ * HIDN};
    cudaGetSymbolAddress(&p, g_hi); float* hi[2] = {(float*)p, (float*)p + (size_t)NI_ * HIDN};
    cudaGetSymbolAddress(&p, g_hp); float* hp[2] = {(float*)p, (float*)p + (size_t)NP_ * HIDN};
    cudaGetSymbolAddress(&p, g_fs);  float* fs  = (float*)p;
    cudaGetSymbolAddress(&p, g_el);  float* el  = (float*)p;
    cudaGetSymbolAddress(&p, g_er);  float* er  = (float*)p;
    cudaGetSymbolAddress(&p, g_eb);  float* eb  = (float*)p;
    cudaGetSymbolAddress(&p, g_wal); float* wal = (float*)p;
    cudaGetSymbolAddress(&p, g_war); float* war = (float*)p;
    cudaGetSymbolAddress(&p, g_wt);  __nv_bfloat16* wt = (__nv_bfloat16*)p;
    cudaGetSymbolAddress(&p, g_rowptr); int* rowptr = (int*)p;
    cudaGetSymbolAddress(&p, g_deg);    int* deg    = (int*)p;
    cudaGetSymbolAddress(&p, g_csrsrc); int* csrsrc = (int*)p;
    cudaGetSymbolAddress(&p, g_cursor); int* cursor = (int*)p;
    cudaGetSymbolAddress(&p, g_bsum);   int* bsum   = (int*)p;

    // enable big dynamic smem for gemm_mma (first call happens outside capture)
    static bool attr_set = false;
    if (!attr_set) {
        cudaFuncSetAttribute(gemm_mma, cudaFuncAttributeMaxDynamicSharedMemorySize, 4 * TILE_B);
        attr_set = true;
    }
    auto wslot = [&](int s) { return wt + (size_t)s * 2 * 16384; };
    auto launch_gemm = [&](const float* A, int slot, int K, const float* bias,
                           float* C, int Nrows, int act) {
        __nv_bfloat16* whi = wslot(slot);
        __nv_bfloat16* wlo = whi + 16384;
        gemm_mma<<<cdiv(Nrows, 128), 256, 4 * TILE_B>>>(A, whi, wlo, bias, C, Nrows, K, act);
    };

    const int Nsrc[4] = {NU_, ND_, NU_, NU_};
    const int Ndst[4] = {ND_, NU_, NI_, NP_};
    const int KP[4] = {128, 64, 64, 64};

    // ---- convert all weights: slots 0-3 proj, 4-7 Wc1, 8-11 Wc2, 12 Wh1 ----
    for (int i = 0; i < 4; i++)
        convert_w<<<cdiv(128 * KP[i], 256), 256>>>(Wp[i], wslot(i), wslot(i) + 16384, KP[i]);
    for (int L = 0; L < 2; L++) {
        const float* Wc = (const float*)d_in[20 + L * 4];
        for (int r = 0; r < 4; r++)
            convert_w<<<64, 256>>>(Wc + (size_t)r * 16384, wslot(4 + L * 4 + r),
                                   wslot(4 + L * 4 + r) + 16384, 128);
    }
    convert_w<<<64, 256>>>(Wh1, wslot(12), wslot(12) + 16384, 128);

    // ---- build CSR for each relation (reused by both layers) ----
    for (int r = 0; r < 4; r++) {
        const int* srcA = eidx[2 * r + 0];
        const int* dstA = eidx[2 * r + 1];
        int nd = Ndst[r];
        int* deg_r = deg + (size_t)r * ND_;
        int* rp_r  = rowptr + (size_t)r * ND_;
        int* cs_r  = csrsrc + (size_t)r * E_;
        cudaMemsetAsync(deg_r, 0, (size_t)nd * sizeof(int));
        hist_k<<<cdiv(E_, 256), 256>>>(dstA, deg_r, E_);
        int nb = cdiv(nd, SCAN_T * SCAN_E);
        scan1_k<<<nb, SCAN_T>>>(deg_r, rp_r, bsum, nd);
        scan2_k<<<1, 256>>>(bsum, nb);
        scan3_k<<<cdiv(nd, 256), 256>>>(rp_r, bsum, nd);
        cudaMemcpyAsync(cursor, rp_r, (size_t)nd * sizeof(int), cudaMemcpyDeviceToDevice);
        scatter_k<<<cdiv(E_, 256), 256>>>(srcA, dstA, cursor, cs_r, E_);
    }

    // ---- input projections -> buffer 0 ----
    launch_gemm(x_user,   0, 128, bpv[0], hu[0], NU_, 0);
    launch_gemm(x_device, 1, 64,  bpv[1], hd[0], ND_, 0);
    launch_gemm(x_ip,     2, 64,  bpv[2], hi[0], NI_, 0);
    launch_gemm(x_phone,  3, 64,  bpv[3], hp[0], NP_, 0);

    for (int L = 0; L < 2; L++) {
        const float* al = (const float*)d_in[21 + L * 4];
        const float* ar = (const float*)d_in[22 + L * 4];
        const float* bc = (const float*)d_in[23 + L * 4];
        const float* Wc = (const float*)d_in[20 + L * 4];
        int in_b = L & 1, out_b = in_b ^ 1;

        prep_attn_w4<<<4, 128>>>(Wc, al, ar, wal, war);

        // relation tables: 0: u->d, 1: d->u, 2: u->i, 3: u->p
        const float* hsrc[4] = {hu[in_b], hd[in_b], hu[in_b], hu[in_b]};
        const float* hdst[4] = {hd[in_b], hu[in_b], hi[in_b], hp[in_b]};
        float* hout[4]       = {hd[out_b], hu[out_b], hi[out_b], hp[out_b]};

        for (int r = 0; r < 4; r++) {
            int* deg_r = deg + (size_t)r * ND_;
            int* rp_r  = rowptr + (size_t)r * ND_;
            int* cs_r  = csrsrc + (size_t)r * E_;

            launch_gemm(hsrc[r], 4 + L * 4 + r, 128, nullptr, fs, Nsrc[r], 0);
            rowdot<<<cdiv(Nsrc[r], 8), 256>>>(hsrc[r], wal + r * 512, nullptr, el, Nsrc[r], 4);
            rowdot<<<cdiv(Ndst[r], 8), 256>>>(hdst[r], war + r * 512, nullptr, er, Ndst[r], 4);

            attn_stats<<<cdiv(Ndst[r], 256), 256>>>(rp_r, deg_r, cs_r, el, er, eb, Ndst[r]);
            attn_aggr<<<cdiv(Ndst[r] * 32, 256), 256>>>(rp_r, deg_r, cs_r, eb, fs,
                                                        bc + r * 128, hout[r], Ndst[r]);
        }
    }

    // head: logits = relu(hu @ Wh1 + bh1) @ Wh2 + bh2   (final user states in buffer 0)
    launch_gemm(hu[0], 12, 128, bh1, fs, NU_, 1);
    rowdot<<<cdiv(NU_, 8), 256>>>(fs, Wh2, bh2, (float*)d_out, NU_, 2);
}

// round 10
// speedup vs baseline: 2.6344x; 1.5064x over previous
#include <cuda_runtime.h>
#include <cuda_bf16.h>
#include <math.h>
#include <stdint.h>

#define NU_ 100000
#define ND_ 150000
#define NI_ 120000
#define NP_ 80000
#define E_  500000
#define HIDN 128

// ---------------- scratch (static device globals; no allocation) ----------------
__device__ float g_hu[2][(size_t)NU_ * HIDN];
__device__ float g_hd[2][(size_t)ND_ * HIDN];
__device__ float g_hi[2][(size_t)NI_ * HIDN];
__device__ float g_hp[2][(size_t)NP_ * HIDN];
__device__ float g_fs4[4][(size_t)ND_ * HIDN];
__device__ float g_eb4[4][(size_t)E_ * 4];
__device__ float g_el4[4][ND_ * 4];
__device__ float g_er4[4][ND_ * 4];
__device__ float g_war2[2][4 * 512];
// transposed/split weights: 13 slots x (hi,lo) x 128*128 bf16
__device__ __nv_bfloat16 g_wt[13 * 2 * 16384];
// CSR scratch (4 relations)
__device__ int g_rowptr[4 * ND_];
__device__ int g_deg[4 * ND_];
__device__ int g_csrsrc[4 * E_];
__device__ int g_cursor4[4][ND_];
__device__ int g_bsum4[4][128];

__device__ __forceinline__ float lrelu(float x) { return x > 0.0f ? x : 0.2f * x; }

__device__ __forceinline__ uint32_t smem_u32(const void* p) {
    uint32_t a;
    asm("{ .reg .u64 t; cvta.to.shared.u64 t, %1; cvt.u32.u64 %0, t; }" : "=r"(a) : "l"(p));
    return a;
}

// ================= warp-level MMA helpers =================
__device__ __forceinline__ void ldm_x4(uint32_t* r, uint32_t addr) {
    asm volatile("ldmatrix.sync.aligned.m8n8.x4.shared.b16 {%0,%1,%2,%3}, [%4];"
                 : "=r"(r[0]), "=r"(r[1]), "=r"(r[2]), "=r"(r[3]) : "r"(addr));
}
__device__ __forceinline__ void mma16816(float* d, const uint32_t* a, const uint32_t* b) {
    asm volatile("mma.sync.aligned.m16n8k16.row.col.f32.bf16.bf16.f32 "
                 "{%0,%1,%2,%3}, {%4,%5,%6,%7}, {%8,%9}, {%0,%1,%2,%3};"
                 : "+f"(d[0]), "+f"(d[1]), "+f"(d[2]), "+f"(d[3])
                 : "r"(a[0]), "r"(a[1]), "r"(a[2]), "r"(a[3]), "r"(b[0]), "r"(b[1]));
}

#define A_STRIDE_B 144
#define A_TILE_B (128 * A_STRIDE_B)

// ============== core GEMM body (device inline): C[N,128]=A[N,K]@W + opts ==============
template <int KC>
__device__ __forceinline__ void gemm_body(
    char* sm, const float* __restrict__ A, const __nv_bfloat16* __restrict__ Bhi,
    const __nv_bfloat16* __restrict__ Blo, const float* __restrict__ bias,
    float* __restrict__ C, int Nrows, int act,
    const float* __restrict__ al_vec, float* __restrict__ el_out, int row0)
{
    const int K = KC;
    const int strideB2 = (K + 8) * 2;
    char* p_bhi = sm;
    char* p_blo = sm + 128 * strideB2;
    char* p_a   = sm + 2 * 128 * strideB2;
    const uint32_t s_b_hi = smem_u32(p_bhi);
    const uint32_t s_b_lo = smem_u32(p_blo);
    const uint32_t s_a = smem_u32(p_a);

    const int tid = threadIdx.x;
    const int wid = tid >> 5;
    const int lane = tid & 31;
    const int warp_m = wid & 3;
    const int warp_n = wid >> 2;

    float acc[2][8][4];
#pragma unroll
    for (int m = 0; m < 2; m++)
#pragma unroll
        for (int n = 0; n < 8; n++)
#pragma unroll
            for (int q = 0; q < 4; q++) acc[m][n][q] = 0.0f;

    const int nchunk = K >> 6;
    const int kvs = (K == 128) ? 5 : 4;
    const int kvm = (1 << kvs) - 1;

    // ---- load B fully (hi & lo): 128 n-rows x (K/4) uint2 loads ----
    // K=128 -> niter=16, K=64 -> niter=8.  (R9 bugfix: loop must reach 16.)
    {
        const int niter = (128 << kvs) >> 8;
#pragma unroll
        for (int it = 0; it < 16; it++) {
            if (it >= niter) break;
            int idx = tid + it * 256;
            int row = idx >> kvs;
            int k4 = (idx & kvm) << 2;
            uint2 vh = *(const uint2*)(Bhi + (size_t)row * K + k4);
            uint2 vl = *(const uint2*)(Blo + (size_t)row * K + k4);
            uint32_t off = (uint32_t)row * strideB2 + (uint32_t)k4 * 2;
            *(uint2*)(p_bhi + off) = vh;
            *(uint2*)(p_blo + off) = vl;
        }
    }

    float4 av[8];
    auto loadA = [&](int kc) {
#pragma unroll
        for (int it = 0; it < 8; it++) {
            int idx = tid + it * 256;
            int row = idx >> 4;
            int k4 = (idx & 15) << 2;
            int gr = row0 + row;
            av[it] = make_float4(0.f, 0.f, 0.f, 0.f);
            if (gr < Nrows) av[it] = *(const float4*)(A + (size_t)gr * K + kc * 64 + k4);
        }
    };
    auto storeA = [&](int stg) {
        char* hi = p_a + stg * (2 * A_TILE_B);
        char* lo = hi + A_TILE_B;
#pragma unroll
        for (int it = 0; it < 8; it++) {
            int idx = tid + it * 256;
            int row = idx >> 4;
            int k4 = (idx & 15) << 2;
            float4 v = av[it];
            __nv_bfloat162 h01 = __floats2bfloat162_rn(v.x, v.y);
            __nv_bfloat162 h23 = __floats2bfloat162_rn(v.z, v.w);
            __nv_bfloat162 l01 = __floats2bfloat162_rn(v.x - __bfloat162float(h01.x),
                                                       v.y - __bfloat162float(h01.y));
            __nv_bfloat162 l23 = __floats2bfloat162_rn(v.z - __bfloat162float(h23.x),
                                                       v.w - __bfloat162float(h23.y));
            uint32_t off = (uint32_t)row * A_STRIDE_B + (uint32_t)k4 * 2;
            *(__nv_bfloat162*)(hi + off) = h01;
            *(__nv_bfloat162*)(hi + off + 4) = h23;
            *(__nv_bfloat162*)(lo + off) = l01;
            *(__nv_bfloat162*)(lo + off + 4) = l23;
        }
    };

    loadA(0);
    storeA(0);
    __syncthreads();

    for (int kc = 0; kc < nchunk; kc++) {
        if (kc + 1 < nchunk) loadA(kc + 1);
        const uint32_t a_hi = s_a + (kc & 1) * (2 * A_TILE_B);
        const uint32_t a_lo = a_hi + A_TILE_B;
#pragma unroll
        for (int ks = 0; ks < 4; ks++) {
            const int k0 = ks * 16;
            uint32_t ah[2][4], al_[2][4];
#pragma unroll
            for (int mt = 0; mt < 2; mt++) {
                int r = warp_m * 32 + mt * 16 + (lane & 7) + ((lane >> 3) & 1) * 8;
                int c = k0 + (lane >> 4) * 8;
                uint32_t off = (uint32_t)r * A_STRIDE_B + (uint32_t)c * 2;
                ldm_x4(ah[mt], a_hi + off);
                ldm_x4(al_[mt], a_lo + off);
            }
            uint32_t bh[4][4], bl[4][4];
#pragma unroll
            for (int pp = 0; pp < 4; pp++) {
                int r = warp_n * 64 + pp * 16 + (lane & 7) + (lane >= 16 ? 8 : 0);
                int c = kc * 64 + k0 + ((lane >> 3) & 1) * 8;
                uint32_t off = (uint32_t)r * strideB2 + (uint32_t)c * 2;
                ldm_x4(bh[pp], s_b_hi + off);
                ldm_x4(bl[pp], s_b_lo + off);
            }
#pragma unroll
            for (int mt = 0; mt < 2; mt++)
#pragma unroll
                for (int pp = 0; pp < 4; pp++)
#pragma unroll
                    for (int hh = 0; hh < 2; hh++) {
                        float* d = acc[mt][pp * 2 + hh];
                        mma16816(d, ah[mt], &bh[pp][hh * 2]);
                        mma16816(d, ah[mt], &bl[pp][hh * 2]);
                        mma16816(d, al_[mt], &bh[pp][hh * 2]);
                    }
        }
        if (kc + 1 < nchunk) storeA((kc + 1) & 1);
        __syncthreads();
    }

#pragma unroll
    for (int mt = 0; mt < 2; mt++) {
        int rbase = row0 + warp_m * 32 + mt * 16 + (lane >> 2);
#pragma unroll
        for (int nt = 0; nt < 8; nt++) {
            int col = warp_n * 64 + nt * 8 + (lane & 3) * 2;
            float2 b2 = make_float2(0.f, 0.f);
            if (bias) b2 = *(const float2*)(bias + col);
            float2 o0 = make_float2(acc[mt][nt][0] + b2.x, acc[mt][nt][1] + b2.y);
            float2 o1 = make_float2(acc[mt][nt][2] + b2.x, acc[mt][nt][3] + b2.y);
            if (act == 1) {
                o0.x = fmaxf(o0.x, 0.f); o0.y = fmaxf(o0.y, 0.f);
                o1.x = fmaxf(o1.x, 0.f); o1.y = fmaxf(o1.y, 0.f);
            }
            if (rbase < Nrows)     *(float2*)(C + (size_t)rbase * HIDN + col) = o0;
            if (rbase + 8 < Nrows) *(float2*)(C + (size_t)(rbase + 8) * HIDN + col) = o1;
        }
        if (el_out) {
            float eA0 = 0.f, eA1 = 0.f, eB0 = 0.f, eB1 = 0.f;
#pragma unroll
            for (int nt = 0; nt < 8; nt++) {
                int col = warp_n * 64 + nt * 8 + (lane & 3) * 2;
                float a0 = __ldg(al_vec + col), a1 = __ldg(al_vec + col + 1);
                float p0 = acc[mt][nt][0] * a0 + acc[mt][nt][1] * a1;
                float p1 = acc[mt][nt][2] * a0 + acc[mt][nt][3] * a1;
                if (nt < 4) { eA0 += p0; eA1 += p1; }
                else        { eB0 += p0; eB1 += p1; }
            }
#pragma unroll
            for (int msk = 1; msk <= 2; msk <<= 1) {
                eA0 += __shfl_xor_sync(0xffffffffu, eA0, msk);
                eA1 += __shfl_xor_sync(0xffffffffu, eA1, msk);
                eB0 += __shfl_xor_sync(0xffffffffu, eB0, msk);
                eB1 += __shfl_xor_sync(0xffffffffu, eB1, msk);
            }
            if ((lane & 3) == 0) {
                if (rbase < Nrows)
                    *(float2*)(el_out + (size_t)rbase * 4 + warp_n * 2) = make_float2(eA0, eB0);
                if (rbase + 8 < Nrows)
                    *(float2*)(el_out + (size_t)(rbase + 8) * 4 + warp_n * 2) = make_float2(eA1, eB1);
            }
        }
    }
}

// ---------------- single GEMM (prologue/head) ----------------
__global__ __launch_bounds__(256) void gemm_mma(
    const float* __restrict__ A, const __nv_bfloat16* __restrict__ Bhi,
    const __nv_bfloat16* __restrict__ Blo, const float* __restrict__ bias,
    float* __restrict__ C, int Nrows, int K, int act)
{
    extern __shared__ char sm[];
    if (K == 128)
        gemm_body<128>(sm, A, Bhi, Blo, bias, C, Nrows, act, nullptr, nullptr, blockIdx.x * 128);
    else
        gemm_body<64>(sm, A, Bhi, Blo, bias, C, Nrows, act, nullptr, nullptr, blockIdx.x * 128);
}

// ---------------- batched conv GEMM: blockIdx.y = relation, K=128, fused el ----------------
struct ConvBatch {
    const float* A[4];
    const __nv_bfloat16* Bh[4];
    const __nv_bfloat16* Bl[4];
    float* C[4];
    const float* alv[4];
    float* elo[4];
    int N[4];
};
__global__ __launch_bounds__(256) void gemm_mma_b(ConvBatch gb)
{
    extern __shared__ char sm[];
    int r = blockIdx.y;
    int row0 = blockIdx.x * 128;
    if (row0 >= gb.N[r]) return;
    gemm_body<128>(sm, gb.A[r], gb.Bh[r], gb.Bl[r], nullptr, gb.C[r], gb.N[r], 0,
                   gb.alv[r], gb.elo[r], row0);
}

// ---------------- batched er rowdot: out[r][row,h] = H[r][row,:] @ war[r][:,h] ----------------
struct RowdotBatch { const float* H[4]; const float* w[4]; float* out[4]; int N[4]; };
__global__ void rowdot_b(RowdotBatch rb)
{
    int r = blockIdx.y;
    __shared__ float ws[512];
    for (int i = threadIdx.x; i < 512; i += blockDim.x) ws[i] = rb.w[r][i];
    __syncthreads();
    int gwarp = (blockIdx.x * blockDim.x + threadIdx.x) >> 5;
    int lane = threadIdx.x & 31;
    if (gwarp >= rb.N[r]) return;
    float4 h = *(const float4*)(rb.H[r] + (size_t)gwarp * HIDN + lane * 4);
    float acc[4] = {0.f, 0.f, 0.f, 0.f};
    const float hv[4] = {h.x, h.y, h.z, h.w};
#pragma unroll
    for (int q = 0; q < 4; q++) {
        int k = lane * 4 + q;
#pragma unroll
        for (int o = 0; o < 4; o++) acc[o] += hv[q] * ws[k * 4 + o];
    }
#pragma unroll
    for (int off = 16; off; off >>= 1)
#pragma unroll
        for (int o = 0; o < 4; o++) acc[o] += __shfl_down_sync(0xffffffffu, acc[o], off);
    if (lane == 0) *(float4*)(rb.out[r] + (size_t)gwarp * 4) = make_float4(acc[0], acc[1], acc[2], acc[3]);
}

// ---------------- plain rowdot (head) ----------------
__global__ void rowdot(const float* __restrict__ Hm, const float* __restrict__ w,
                       const float* __restrict__ bias, float* __restrict__ out,
                       int N, int NOUT)
{
    __shared__ float ws[512];
    for (int i = threadIdx.x; i < 128 * NOUT; i += blockDim.x) ws[i] = w[i];
    __syncthreads();
    int gwarp = (blockIdx.x * blockDim.x + threadIdx.x) >> 5;
    int lane = threadIdx.x & 31;
    if (gwarp >= N) return;
    float4 h = *(const float4*)(Hm + (size_t)gwarp * HIDN + lane * 4);
    float acc[4] = {0.f, 0.f, 0.f, 0.f};
    const float hv[4] = {h.x, h.y, h.z, h.w};
#pragma unroll
    for (int q = 0; q < 4; q++) {
        int k = lane * 4 + q;
        for (int o = 0; o < NOUT; o++) acc[o] += hv[q] * ws[k * NOUT + o];
    }
#pragma unroll
    for (int off = 16; off; off >>= 1)
        for (int o = 0; o < 4; o++) acc[o] += __shfl_down_sync(0xffffffffu, acc[o], off);
    if (lane == 0)
        for (int o = 0; o < NOUT; o++)
            out[(size_t)gwarp * NOUT + o] = acc[o] + (bias ? bias[o] : 0.0f);
}

// ---------------- batched weight convert: blockIdx.y = slot ----------------
struct WBatch { const float* W[13]; int K[13]; };
__global__ void convert_w_b(WBatch wb, __nv_bfloat16* __restrict__ wt)
{
    int s = blockIdx.y;
    int K = wb.K[s];
    int i = blockIdx.x * blockDim.x + threadIdx.x;
    if (i >= 128 * K) return;
    int n = i / K, k = i - n * K;
    float v = wb.W[s][(size_t)k * 128 + n];
    __nv_bfloat16 h = __float2bfloat16(v);
    __nv_bfloat16* hi = wt + (size_t)s * 2 * 16384;
    hi[i] = h;
    hi[16384 + i] = __float2bfloat16(v - __bfloat162float(h));
}

// ---------------- fold ar into W ----------------
__global__ void prep_war(const float* __restrict__ Wc, const float* __restrict__ ar,
                         float* __restrict__ war)
{
    int r = blockIdx.x;
    int k = threadIdx.x;
    const float* W = Wc + (size_t)r * 128 * 128;
    const float* arr = ar + r * 128;
#pragma unroll
    for (int h = 0; h < 4; h++) {
        float sr = 0.f;
#pragma unroll
        for (int d = 0; d < 32; d++) sr += W[k * 128 + h * 32 + d] * arr[h * 32 + d];
        war[r * 512 + k * 4 + h] = sr;
    }
}

// ---------------- batched CSR build ----------------
struct CsrBatch {
    const int* src[4]; const int* dst[4];
    int* deg[4]; int* rp[4]; int* cs[4]; int* cur[4]; int* bs[4];
    int Nd[4];
};
__global__ void zero_deg_b(CsrBatch cb) {
    int r = blockIdx.y;
    int i = blockIdx.x * blockDim.x + threadIdx.x;
    if (i < cb.Nd[r]) cb.deg[r][i] = 0;
}
__global__ void hist_b(CsrBatch cb) {
    int r = blockIdx.y;
    int e = blockIdx.x * blockDim.x + threadIdx.x;
    if (e < E_) atomicAdd(&cb.deg[r][cb.dst[r][e]], 1);
}
#define SCAN_T 256
#define SCAN_E 8
__global__ void scan1_b(CsrBatch cb) {
    int r = blockIdx.y;
    int n = cb.Nd[r];
    const int* in = cb.deg[r];
    int* out = cb.rp[r];
    __shared__ int sm[SCAN_T];
    int base = blockIdx.x * SCAN_T * SCAN_E + threadIdx.x * SCAN_E;
    int v[SCAN_E];
    int s = 0;
#pragma unroll
    for (int i = 0; i < SCAN_E; i++) {
        v[i] = (base + i < n) ? in[base + i] : 0;
        s += v[i];
    }
    sm[threadIdx.x] = s;
    __syncthreads();
    for (int off = 1; off < SCAN_T; off <<= 1) {
        int t = (threadIdx.x >= off) ? sm[threadIdx.x - off] : 0;
        __syncthreads();
        sm[threadIdx.x] += t;
        __syncthreads();
    }
    int run = sm[threadIdx.x] - s;
#pragma unroll
    for (int i = 0; i < SCAN_E; i++) {
        if (base + i < n) out[base + i] = run;
        run += v[i];
    }
    if (threadIdx.x == SCAN_T - 1) cb.bs[r][blockIdx.x] = sm[SCAN_T - 1];
}
__global__ void scan2_b(CsrBatch cb, int nb) {
    int r = blockIdx.x;
    __shared__ int sm[128];
    int v = (threadIdx.x < nb) ? cb.bs[r][threadIdx.x] : 0;
    sm[threadIdx.x] = v;
    __syncthreads();
    for (int off = 1; off < 128; off <<= 1) {
        int t = (threadIdx.x >= off) ? sm[threadIdx.x - off] : 0;
        __syncthreads();
        sm[threadIdx.x] += t;
        __syncthreads();
    }
    if (threadIdx.x < nb) cb.bs[r][threadIdx.x] = sm[threadIdx.x] - v;
}
__global__ void scan3_b(CsrBatch cb) {
    int r = blockIdx.y;
    int i = blockIdx.x * blockDim.x + threadIdx.x;
    if (i < cb.Nd[r]) {
        int v = cb.rp[r][i] + cb.bs[r][i / (SCAN_T * SCAN_E)];
        cb.rp[r][i] = v;
        cb.cur[r][i] = v;     // cursor copy fused here
    }
}
__global__ void scatter_b(CsrBatch cb) {
    int r = blockIdx.y;
    int e = blockIdx.x * blockDim.x + threadIdx.x;
    if (e >= E_) return;
    int dn = cb.dst[r][e];
    int pos = atomicAdd(&cb.cur[r][dn], 1);
    cb.cs[r][pos] = cb.src[r][e];
}

// ---------------- batched attention stats ----------------
struct StatsBatch {
    const int* rp[4]; const int* dg[4]; const int* cs[4];
    const float* el[4]; const float* er[4]; float* eb[4];
    int Nd[4];
};
__global__ void attn_stats_b(StatsBatch sb)
{
    int r = blockIdx.y;
    int d = blockIdx.x * blockDim.x + threadIdx.x;
    if (d >= sb.Nd[r]) return;
    int dg = sb.dg[r][d];
    if (dg == 0) return;
    int st = sb.rp[r][d];
    const int* cs = sb.cs[r];
    const float* el = sb.el[r];
    float* eb = sb.eb[r];
    float4 r4 = *(const float4*)(sb.er[r] + (size_t)d * 4);
    float m[4] = {-INFINITY, -INFINITY, -INFINITY, -INFINITY};
    float s[4] = {0.f, 0.f, 0.f, 0.f};
    for (int j = 0; j < dg; j++) {
        int sn = cs[st + j];
        float4 l4 = *(const float4*)(el + (size_t)sn * 4);
        float e[4];
        e[0] = lrelu(l4.x + r4.x); e[1] = lrelu(l4.y + r4.y);
        e[2] = lrelu(l4.z + r4.z); e[3] = lrelu(l4.w + r4.w);
        *(float4*)(eb + (size_t)(st + j) * 4) = make_float4(e[0], e[1], e[2], e[3]);
#pragma unroll
        for (int h = 0; h < 4; h++) {
            if (e[h] > m[h]) { s[h] = s[h] * __expf(m[h] - e[h]) + 1.0f; m[h] = e[h]; }
            else             { s[h] += __expf(e[h] - m[h]); }
        }
    }
    float inv[4];
#pragma unroll
    for (int h = 0; h < 4; h++) inv[h] = 1.0f / s[h];
    for (int j = 0; j < dg; j++) {
        float4 v = *(float4*)(eb + (size_t)(st + j) * 4);
        v.x = __expf(v.x - m[0]) * inv[0];
        v.y = __expf(v.y - m[1]) * inv[1];
        v.z = __expf(v.z - m[2]) * inv[2];
        v.w = __expf(v.w - m[3]) * inv[3];
        *(float4*)(eb + (size_t)(st + j) * 4) = v;
    }
}

// ---------------- batched aggregate + bias + ELU ----------------
struct AggrBatch {
    const int* rp[4]; const int* dg[4]; const int* cs[4];
    const float* eb[4]; const float* fs[4]; const float* bc;
    float* out[4];
    int Nd[4];
};
__global__ void attn_aggr_b(AggrBatch ab)
{
    int r = blockIdx.y;
    int gid = blockIdx.x * blockDim.x + threadIdx.x;
    int w = gid >> 5, l = gid & 31;
    if (w >= ab.Nd[r]) return;
    int st = ab.rp[r][w], dg = ab.dg[r][w];
    const int* cs = ab.cs[r];
    const float* eb = ab.eb[r];
    const float* fs = ab.fs[r];
    int h = l >> 3;
    float4 acc = make_float4(0.f, 0.f, 0.f, 0.f);
    for (int j = 0; j < dg; j++) {
        int sn = __ldg(&cs[st + j]);
        float a = __ldg(&eb[(size_t)(st + j) * 4 + h]);
        float4 f = *(const float4*)(fs + (size_t)sn * HIDN + l * 4);
        acc.x += a * f.x; acc.y += a * f.y;
        acc.z += a * f.z; acc.w += a * f.w;
    }
    float4 b4 = *(const float4*)(ab.bc + r * 128 + l * 4);
    acc.x += b4.x; acc.y += b4.y; acc.z += b4.z; acc.w += b4.w;
    acc.x = acc.x > 0.f ? acc.x : expm1f(acc.x);
    acc.y = acc.y > 0.f ? acc.y : expm1f(acc.y);
    acc.z = acc.z > 0.f ? acc.z : expm1f(acc.z);
    acc.w = acc.w > 0.f ? acc.w : expm1f(acc.w);
    *(float4*)(ab.out[r] + (size_t)w * HIDN + l * 4) = acc;
}

// ---------------- host orchestration ----------------
static inline int cdiv(int a, int b) { return (a + b - 1) / b; }

extern "C" void kernel_launch(void* const* d_in, const int* in_sizes, int n_in,
                              void* d_out, int out_size)
{
    (void)in_sizes; (void)n_in; (void)out_size;
    const float* xin[4] = {(const float*)d_in[0], (const float*)d_in[1],
                           (const float*)d_in[2], (const float*)d_in[3]};
    const int* eidx[8];
    for (int i = 0; i < 8; i++) eidx[i] = (const int*)d_in[4 + i];

    const float* Wp[4]  = {(const float*)d_in[12], (const float*)d_in[14],
                           (const float*)d_in[16], (const float*)d_in[18]};
    const float* bpv[4] = {(const float*)d_in[13], (const float*)d_in[15],
                           (const float*)d_in[17], (const float*)d_in[19]};
    const float* Wh1 = (const float*)d_in[28]; const float* bh1 = (const float*)d_in[29];
    const float* Wh2 = (const float*)d_in[30]; const float* bh2 = (const float*)d_in[31];

    void* p;
    cudaGetSymbolAddress(&p, g_hu); float* hu[2] = {(float*)p, (float*)p + (size_t)NU_ * HIDN};
    cudaGetSymbolAddress(&p, g_hd); float* hd[2] = {(float*)p, (float*)p + (size_t)ND_ * HIDN};
    cudaGetSymbolAddress(&p, g_hi); float* hi[2] = {(float*)p, (float*)p + (size_t)NI_ * HIDN};
    cudaGetSymbolAddress(&p, g_hp); float* hp[2] = {(float*)p, (float*)p + (size_t)NP_ * HIDN};
    cudaGetSymbolAddress(&p, g_fs4); float* fs4 = (float*)p;
    cudaGetSymbolAddress(&p, g_eb4); float* eb4 = (float*)p;
    cudaGetSymbolAddress(&p, g_el4); float* el4 = (float*)p;
    cudaGetSymbolAddress(&p, g_er4); float* er4 = (float*)p;
    cudaGetSymbolAddress(&p, g_war2); float* war2 = (float*)p;
    cudaGetSymbolAddress(&p, g_wt);  __nv_bfloat16* wt = (__nv_bfloat16*)p;
    cudaGetSymbolAddress(&p, g_rowptr); int* rowptr = (int*)p;
    cudaGetSymbolAddress(&p, g_deg);    int* deg    = (int*)p;
    cudaGetSymbolAddress(&p, g_csrsrc); int* csrsrc = (int*)p;
    cudaGetSymbolAddress(&p, g_cursor4); int* cursor4 = (int*)p;
    cudaGetSymbolAddress(&p, g_bsum4);   int* bsum4   = (int*)p;

    // set attributes ONCE, outside graph capture (first call is the correctness run)
    static bool attr_set = false;
    if (!attr_set) {
        cudaFuncSetAttribute(gemm_mma,   cudaFuncAttributeMaxDynamicSharedMemorySize, 144 * 1024);
        cudaFuncSetAttribute(gemm_mma_b, cudaFuncAttributeMaxDynamicSharedMemorySize, 144 * 1024);
        attr_set = true;
    }

    const int Nsrc[4] = {NU_, ND_, NU_, NU_};
    const int Ndst[4] = {ND_, NU_, NI_, NP_};
    const int Nnode[4] = {NU_, ND_, NI_, NP_};
    const int KP[4] = {128, 64, 64, 64};

    auto wslot = [&](int s) { return wt + (size_t)s * 2 * 16384; };
    auto smem_for = [&](int K) { return (size_t)2 * 128 * (K + 8) * 2 + 4 * A_TILE_B; };

    // ---- batched weight conversion (slots 0-3 proj, 4-7 Wc1, 8-11 Wc2, 12 Wh1) ----
    {
        WBatch wb;
        for (int r = 0; r < 4; r++) { wb.W[r] = Wp[r]; wb.K[r] = KP[r]; }
        const float* Wc1 = (const float*)d_in[20];
        const float* Wc2 = (const float*)d_in[24];
        for (int r = 0; r < 4; r++) {
            wb.W[4 + r] = Wc1 + (size_t)r * 16384; wb.K[4 + r] = 128;
            wb.W[8 + r] = Wc2 + (size_t)r * 16384; wb.K[8 + r] = 128;
        }
        wb.W[12] = Wh1; wb.K[12] = 128;
        convert_w_b<<<dim3(64, 13), 256>>>(wb, wt);
    }
    prep_war<<<4, 128>>>((const float*)d_in[20], (const float*)d_in[22], war2);
    prep_war<<<4, 128>>>((const float*)d_in[24], (const float*)d_in[26], war2 + 4 * 512);

    // ---- batched CSR build ----
    CsrBatch cb;
    for (int r = 0; r < 4; r++) {
        cb.src[r] = eidx[2 * r + 0];
        cb.dst[r] = eidx[2 * r + 1];
        cb.deg[r] = deg + (size_t)r * ND_;
        cb.rp[r]  = rowptr + (size_t)r * ND_;
        cb.cs[r]  = csrsrc + (size_t)r * E_;
        cb.cur[r] = cursor4 + (size_t)r * ND_;
        cb.bs[r]  = bsum4 + (size_t)r * 128;
        cb.Nd[r]  = Ndst[r];
    }
    int nb = cdiv(ND_, SCAN_T * SCAN_E);   // 74 blocks max (<=128)
    zero_deg_b<<<dim3(cdiv(ND_, 256), 4), 256>>>(cb);
    hist_b<<<dim3(cdiv(E_, 256), 4), 256>>>(cb);
    scan1_b<<<dim3(nb, 4), SCAN_T>>>(cb);
    scan2_b<<<4, 128>>>(cb, nb);
    scan3_b<<<dim3(cdiv(ND_, 256), 4), 256>>>(cb);
    scatter_b<<<dim3(cdiv(E_, 256), 4), 256>>>(cb);

    // ---- input projections (sequential; each fills the chip) ----
    for (int r = 0; r < 4; r++) {
        float* dst0 = (r == 0) ? hu[0] : (r == 1) ? hd[0] : (r == 2) ? hi[0] : hp[0];
        gemm_mma<<<cdiv(Nnode[r], 128), 256, smem_for(KP[r])>>>(
            xin[r], wslot(r), wslot(r) + 16384, bpv[r], dst0, Nnode[r], KP[r], 0);
    }

    // ---- 2 conv layers, batched across relations ----
    const int maxNs = ND_, maxNd = ND_;
    for (int L = 0; L < 2; L++) {
        const float* al = (const float*)d_in[21 + L * 4];
        const float* bc = (const float*)d_in[23 + L * 4];
        int in_b = L & 1, out_b = in_b ^ 1;

        const float* hsrc[4] = {hu[in_b], hd[in_b], hu[in_b], hu[in_b]};
        const float* hdst[4] = {hd[in_b], hu[in_b], hi[in_b], hp[in_b]};
        float* hout[4]       = {hd[out_b], hu[out_b], hi[out_b], hp[out_b]};

        RowdotBatch rb;
        ConvBatch gb;
        StatsBatch sb;
        AggrBatch ab;
        for (int r = 0; r < 4; r++) {
            float* fs_r = fs4 + (size_t)r * ND_ * HIDN;
            float* eb_r = eb4 + (size_t)r * E_ * 4;
            float* el_r = el4 + (size_t)r * ND_ * 4;
            float* er_r = er4 + (size_t)r * ND_ * 4;

            rb.H[r] = hdst[r]; rb.w[r] = war2 + (size_t)L * 4 * 512 + r * 512;
            rb.out[r] = er_r;  rb.N[r] = Ndst[r];

            gb.A[r] = hsrc[r];
            gb.Bh[r] = wslot(4 + L * 4 + r); gb.Bl[r] = wslot(4 + L * 4 + r) + 16384;
            gb.C[r] = fs_r; gb.alv[r] = al + r * 128; gb.elo[r] = el_r; gb.N[r] = Nsrc[r];

            sb.rp[r] = cb.rp[r]; sb.dg[r] = cb.deg[r]; sb.cs[r] = cb.cs[r];
            sb.el[r] = el_r; sb.er[r] = er_r; sb.eb[r] = eb_r; sb.Nd[r] = Ndst[r];

            ab.rp[r] = cb.rp[r]; ab.dg[r] = cb.deg[r]; ab.cs[r] = cb.cs[r];
            ab.eb[r] = eb_r; ab.fs[r] = fs_r; ab.out[r] = hout[r]; ab.Nd[r] = Ndst[r];
        }
        ab.bc = bc;

        rowdot_b<<<dim3(cdiv(maxNd, 8), 4), 256>>>(rb);
        gemm_mma_b<<<dim3(cdiv(maxNs, 128), 4), 256, smem_for(128)>>>(gb);
        attn_stats_b<<<dim3(cdiv(maxNd, 256), 4), 256>>>(sb);
        attn_aggr_b<<<dim3(cdiv(maxNd, 8), 4), 256>>>(ab);
    }

    // ---- head ----
    gemm_mma<<<cdiv(NU_, 128), 256, smem_for(128)>>>(
        hu[0], wslot(12), wslot(12) + 16384, bh1, fs4, NU_, 128, 1);
    rowdot<<<cdiv(NU_, 8), 256>>>(fs4, Wh2, bh2, (float*)d_out, NU_, 2);
}